// round 2
// baseline (speedup 1.0000x reference)
#include <cuda_runtime.h>
#include <math.h>

#define N_ROWS 16384
#define C_ROWS 10000
#define D_DIM  256
#define EPS    1e-6f

// Scratch for inverse norms (allocation-free rule: __device__ globals)
__device__ float g_inv_xn[N_ROWS];
__device__ float g_inv_pn[C_ROWS];

// One warp per row: 256 floats = 64 float4, 32 lanes x 2 float4 each.
__global__ void row_inv_norm_kernel(const float* __restrict__ src,
                                    float* __restrict__ dst, int rows) {
    int warp = (blockIdx.x * blockDim.x + threadIdx.x) >> 5;
    int lane = threadIdx.x & 31;
    if (warp >= rows) return;
    const float4* p = reinterpret_cast<const float4*>(src + (size_t)warp * D_DIM);
    float sum = 0.f;
#pragma unroll
    for (int i = 0; i < 2; i++) {
        float4 v = p[lane + 32 * i];
        sum = fmaf(v.x, v.x, sum);
        sum = fmaf(v.y, v.y, sum);
        sum = fmaf(v.z, v.z, sum);
        sum = fmaf(v.w, v.w, sum);
    }
#pragma unroll
    for (int o = 16; o > 0; o >>= 1)
        sum += __shfl_xor_sync(0xffffffffu, sum, o);
    if (lane == 0) dst[warp] = 1.0f / fmaxf(sqrtf(sum), EPS);
}

// 128x128x8 SGEMM (NT: both operands K-contiguous), fused cosine epilogue.
// 256 threads, each computes an 8x8 micro-tile.
#define BM 128
#define BN 128
#define BK 8
#define TM 8
#define TN 8

__global__ __launch_bounds__(256, 2)
void cosine_gemm_kernel(const float* __restrict__ X,   // [N_ROWS, D]
                        const float* __restrict__ P,   // [C_ROWS, D]
                        const float* __restrict__ inv_xn,
                        const float* __restrict__ inv_pn,
                        float* __restrict__ out) {     // [N_ROWS, C_ROWS]
    __shared__ float As[BK][BM];
    __shared__ float Bs[BK][BN];

    const int tid = threadIdx.x;
    const int bm = blockIdx.y;   // row tile
    const int bn = blockIdx.x;   // col tile

    const int m0 = bm * BM;
    const int n0 = bn * BN;

    // Loader mapping: 256 threads load 128 rows x 8 k (1024 floats) = 1 float4 each.
    const int ldRow = tid >> 1;          // 0..127
    const int ldCol = (tid & 1) * 4;     // 0 or 4

    // Compute mapping
    const int tm = (tid >> 4) * TM;      // 0..120 step 8
    const int tn = (tid & 15) * TN;      // 0..120 step 8

    float acc[TM][TN];
#pragma unroll
    for (int i = 0; i < TM; i++)
#pragma unroll
        for (int j = 0; j < TN; j++) acc[i][j] = 0.f;

    const int aRow = m0 + ldRow;                 // always < N_ROWS (16384 % 128 == 0)
    const int bRow = n0 + ldRow;                 // may exceed C_ROWS
    const bool bValid = (bRow < C_ROWS);

    for (int k0 = 0; k0 < D_DIM; k0 += BK) {
        // Load A tile, store transposed
        float4 av = *reinterpret_cast<const float4*>(X + (size_t)aRow * D_DIM + k0 + ldCol);
        As[ldCol + 0][ldRow] = av.x;
        As[ldCol + 1][ldRow] = av.y;
        As[ldCol + 2][ldRow] = av.z;
        As[ldCol + 3][ldRow] = av.w;

        // Load B tile (prototypes), zero-pad past C_ROWS
        float4 bv = make_float4(0.f, 0.f, 0.f, 0.f);
        if (bValid)
            bv = *reinterpret_cast<const float4*>(P + (size_t)bRow * D_DIM + k0 + ldCol);
        Bs[ldCol + 0][ldRow] = bv.x;
        Bs[ldCol + 1][ldRow] = bv.y;
        Bs[ldCol + 2][ldRow] = bv.z;
        Bs[ldCol + 3][ldRow] = bv.w;

        __syncthreads();

#pragma unroll
        for (int k = 0; k < BK; k++) {
            float ar[TM], br[TN];
            float4 a0 = *reinterpret_cast<const float4*>(&As[k][tm]);
            float4 a1 = *reinterpret_cast<const float4*>(&As[k][tm + 4]);
            ar[0] = a0.x; ar[1] = a0.y; ar[2] = a0.z; ar[3] = a0.w;
            ar[4] = a1.x; ar[5] = a1.y; ar[6] = a1.z; ar[7] = a1.w;
            float4 b0 = *reinterpret_cast<const float4*>(&Bs[k][tn]);
            float4 b1 = *reinterpret_cast<const float4*>(&Bs[k][tn + 4]);
            br[0] = b0.x; br[1] = b0.y; br[2] = b0.z; br[3] = b0.w;
            br[4] = b1.x; br[5] = b1.y; br[6] = b1.z; br[7] = b1.w;
#pragma unroll
            for (int i = 0; i < TM; i++)
#pragma unroll
                for (int j = 0; j < TN; j++)
                    acc[i][j] = fmaf(ar[i], br[j], acc[i][j]);
        }
        __syncthreads();
    }

    // Epilogue: scale by 1/(|x| * |p|), float4 stores (C_ROWS % 4 == 0)
    float ixn[TM];
#pragma unroll
    for (int i = 0; i < TM; i++) ixn[i] = inv_xn[m0 + tm + i];

    float ipn[TN];
#pragma unroll
    for (int j = 0; j < TN; j++) {
        int col = n0 + tn + j;
        ipn[j] = (col < C_ROWS) ? inv_pn[col] : 0.f;
    }

#pragma unroll
    for (int i = 0; i < TM; i++) {
        const int row = m0 + tm + i;
        float* orow = out + (size_t)row * C_ROWS;
#pragma unroll
        for (int j4 = 0; j4 < TN; j4 += 4) {
            int col = n0 + tn + j4;
            if (col < C_ROWS) {
                float4 v;
                v.x = acc[i][j4 + 0] * ixn[i] * ipn[j4 + 0];
                v.y = acc[i][j4 + 1] * ixn[i] * ipn[j4 + 1];
                v.z = acc[i][j4 + 2] * ixn[i] * ipn[j4 + 2];
                v.w = acc[i][j4 + 3] * ixn[i] * ipn[j4 + 3];
                *reinterpret_cast<float4*>(orow + col) = v;
            }
        }
    }
}

extern "C" void kernel_launch(void* const* d_in, const int* in_sizes, int n_in,
                              void* d_out, int out_size) {
    const float* x = (const float*)d_in[0];          // [16384, 256]
    const float* protos = (const float*)d_in[1];     // [10000, 256]
    float* out = (float*)d_out;                      // [16384, 10000]

    float* inv_xn;
    float* inv_pn;
    cudaGetSymbolAddress((void**)&inv_xn, g_inv_xn);
    cudaGetSymbolAddress((void**)&inv_pn, g_inv_pn);

    // Inverse norms: one warp per row, 256-thread blocks (8 warps)
    {
        int blocks = (N_ROWS * 32 + 255) / 256;
        row_inv_norm_kernel<<<blocks, 256>>>(x, inv_xn, N_ROWS);
    }
    {
        int blocks = (C_ROWS * 32 + 255) / 256;
        row_inv_norm_kernel<<<blocks, 256>>>(protos, inv_pn, C_ROWS);
    }

    dim3 grid((C_ROWS + BN - 1) / BN, N_ROWS / BM);  // (79, 128)
    cosine_gemm_kernel<<<grid, 256>>>(x, protos, inv_xn, inv_pn, out);
}

// round 4
// speedup vs baseline: 3.2739x; 3.2739x over previous
#include <cuda_runtime.h>
#include <cuda_bf16.h>
#include <cstdint>
#include <math.h>

#define N_ROWS 16384
#define C_ROWS 10000
#define D_DIM  256
#define KE     768          // expanded K: (hi,hi,lo) x (hi,lo,hi)
#define EPS    1e-6f

#define BM 128
#define BN 128
#define BK 64               // K elements per chunk (128 bytes per row)
#define NCHUNK (KE / BK)    // 12
#define STAGES 3
#define STAGE_BYTES 32768   // 16KB A + 16KB B
#define SMEM_TOTAL (STAGES * STAGE_BYTES)

// ---------------- device scratch (allocation-free rule) ----------------
__device__ float g_inv_xn[N_ROWS];
__device__ float g_inv_pn[C_ROWS];
__device__ __nv_bfloat16 g_Xs[(size_t)N_ROWS * KE];
__device__ __nv_bfloat16 g_Ps[(size_t)C_ROWS * KE];

// ---------------- helpers ----------------
__device__ __forceinline__ uint32_t smem_u32(const void* p) {
    uint32_t a;
    asm("{ .reg .u64 t; cvta.to.shared.u64 t, %1; cvt.u32.u64 %0, t; }" : "=r"(a) : "l"(p));
    return a;
}

__device__ __forceinline__ void cp_async16(uint32_t dst, const void* src, uint32_t src_bytes) {
    asm volatile("cp.async.cg.shared.global [%0], [%1], 16, %2;"
                 :: "r"(dst), "l"(src), "r"(src_bytes) : "memory");
}
#define CP_COMMIT() asm volatile("cp.async.commit_group;" ::: "memory")
template <int N>
__device__ __forceinline__ void cp_wait() {
    asm volatile("cp.async.wait_group %0;" :: "n"(N) : "memory");
}

__device__ __forceinline__ uint32_t sw128(uint32_t off) { return off ^ ((off >> 3) & 0x70); }

__device__ __forceinline__ void ldsm_x4(uint32_t* r, uint32_t addr) {
    asm volatile("ldmatrix.sync.aligned.m8n8.x4.shared.b16 {%0,%1,%2,%3}, [%4];"
                 : "=r"(r[0]), "=r"(r[1]), "=r"(r[2]), "=r"(r[3]) : "r"(addr));
}
__device__ __forceinline__ void ldsm_x2(uint32_t* r, uint32_t addr) {
    asm volatile("ldmatrix.sync.aligned.m8n8.x2.shared.b16 {%0,%1}, [%2];"
                 : "=r"(r[0]), "=r"(r[1]) : "r"(addr));
}
__device__ __forceinline__ void mma_bf16(float* d, const uint32_t* a, const uint32_t* b) {
    asm volatile("mma.sync.aligned.m16n8k16.row.col.f32.bf16.bf16.f32 "
                 "{%0,%1,%2,%3}, {%4,%5,%6,%7}, {%8,%9}, {%0,%1,%2,%3};"
                 : "+f"(d[0]), "+f"(d[1]), "+f"(d[2]), "+f"(d[3])
                 : "r"(a[0]), "r"(a[1]), "r"(a[2]), "r"(a[3]), "r"(b[0]), "r"(b[1]));
}

// ---------------- norm kernel ----------------
__global__ void row_inv_norm_kernel(const float* __restrict__ src,
                                    float* __restrict__ dst, int rows) {
    int warp = (blockIdx.x * blockDim.x + threadIdx.x) >> 5;
    int lane = threadIdx.x & 31;
    if (warp >= rows) return;
    const float4* p = reinterpret_cast<const float4*>(src + (size_t)warp * D_DIM);
    float sum = 0.f;
#pragma unroll
    for (int i = 0; i < 2; i++) {
        float4 v = p[lane + 32 * i];
        sum = fmaf(v.x, v.x, sum); sum = fmaf(v.y, v.y, sum);
        sum = fmaf(v.z, v.z, sum); sum = fmaf(v.w, v.w, sum);
    }
#pragma unroll
    for (int o = 16; o > 0; o >>= 1) sum += __shfl_xor_sync(0xffffffffu, sum, o);
    if (lane == 0) dst[warp] = 1.0f / fmaxf(sqrtf(sum), EPS);
}

// ---------------- hi/lo split conversion ----------------
// mode 0 (X): cols [0,256)=hi  [256,512)=hi  [512,768)=lo
// mode 1 (P): cols [0,256)=hi  [256,512)=lo  [512,768)=hi
template <int MODE>
__global__ void convert_split_kernel(const float* __restrict__ src,
                                     __nv_bfloat16* __restrict__ dst, int rows) {
    int idx = blockIdx.x * blockDim.x + threadIdx.x;   // one per 4 elems
    int total = rows * (D_DIM / 4);
    if (idx >= total) return;
    int r = idx / (D_DIM / 4);
    int c = (idx % (D_DIM / 4)) * 4;
    float4 v = *reinterpret_cast<const float4*>(src + (size_t)r * D_DIM + c);
    float f[4] = {v.x, v.y, v.z, v.w};
    __nv_bfloat16 hi[4], lo[4];
#pragma unroll
    for (int i = 0; i < 4; i++) {
        hi[i] = __float2bfloat16_rn(f[i]);
        lo[i] = __float2bfloat16_rn(f[i] - __bfloat162float(hi[i]));
    }
    __nv_bfloat162 h01, h23, l01, l23;
    h01.x = hi[0]; h01.y = hi[1]; h23.x = hi[2]; h23.y = hi[3];
    l01.x = lo[0]; l01.y = lo[1]; l23.x = lo[2]; l23.y = lo[3];
    __nv_bfloat16* row = dst + (size_t)r * KE + c;
    *reinterpret_cast<__nv_bfloat162*>(row) = h01;
    *reinterpret_cast<__nv_bfloat162*>(row + 2) = h23;
    if (MODE == 0) {        // X: hi, hi, lo
        *reinterpret_cast<__nv_bfloat162*>(row + 256) = h01;
        *reinterpret_cast<__nv_bfloat162*>(row + 258) = h23;
        *reinterpret_cast<__nv_bfloat162*>(row + 512) = l01;
        *reinterpret_cast<__nv_bfloat162*>(row + 514) = l23;
    } else {                // P: hi, lo, hi
        *reinterpret_cast<__nv_bfloat162*>(row + 256) = l01;
        *reinterpret_cast<__nv_bfloat162*>(row + 258) = l23;
        *reinterpret_cast<__nv_bfloat162*>(row + 512) = h01;
        *reinterpret_cast<__nv_bfloat162*>(row + 514) = h23;
    }
}

// ---------------- HMMA bf16 GEMM with fused cosine epilogue ----------------
// 128x128 tile, 8 warps in 2(M) x 4(N) layout, each warp 64x32.
__global__ __launch_bounds__(256, 2)
void cosine_hmma_kernel(const __nv_bfloat16* __restrict__ Xs,
                        const __nv_bfloat16* __restrict__ Ps,
                        const float* __restrict__ inv_xn,
                        const float* __restrict__ inv_pn,
                        float* __restrict__ out) {
    extern __shared__ __align__(1024) char smem[];
    const uint32_t sb = smem_u32(smem);
    const int tid = threadIdx.x;
    const int wid = tid >> 5;
    const int lane = tid & 31;
    const int m0 = blockIdx.y * BM;
    const int n0 = blockIdx.x * BN;

    const int wm = (wid & 1) * 64;    // warp M offset
    const int wn = (wid >> 1) * 32;   // warp N offset

    // Per-lane ldmatrix row offsets (within tile) and xor selectors.
    uint32_t aBase[4], bBase[4];
    uint32_t aSel[4], bSel[4];
#pragma unroll
    for (int im = 0; im < 4; im++) {
        int rA = wm + im * 16 + (lane & 15);
        aBase[im] = rA * 128;
        aSel[im] = rA & 7;
    }
#pragma unroll
    for (int in = 0; in < 4; in++) {
        int rB = wn + in * 8 + (lane & 7);
        bBase[in] = 16384 + rB * 128;
        bSel[in] = rB & 7;
    }
    const uint32_t hiA = lane >> 4;          // 0/1: k half for A ldmatrix
    const uint32_t hiB = (lane >> 3) & 1;    // 0/1: k half for B ldmatrix

    float acc[4][4][4];
#pragma unroll
    for (int im = 0; im < 4; im++)
#pragma unroll
        for (int in = 0; in < 4; in++)
#pragma unroll
            for (int q = 0; q < 4; q++) acc[im][in][q] = 0.f;

    // ---- chunk loader: A tile 128x64 (16KB), B tile 128x64 (16KB) ----
    auto load_chunk = [&](int c, int s) {
        const int cb = c * BK;
        const uint32_t aA = sb + s * STAGE_BYTES;
        const uint32_t bA = aA + 16384;
#pragma unroll
        for (int i = 0; i < 4; i++) {
            int u = tid + i * 256;
            int row = u >> 3, ch = u & 7;
            const char* g = (const char*)(Xs + (size_t)(m0 + row) * KE + cb) + ch * 16;
            cp_async16(aA + sw128(row * 128 + ch * 16), g, 16);
        }
#pragma unroll
        for (int i = 0; i < 4; i++) {
            int u = tid + i * 256;
            int row = u >> 3, ch = u & 7;
            int pr = n0 + row;
            uint32_t ok = (pr < C_ROWS) ? 16u : 0u;
            const char* g = (const char*)(Ps + (size_t)(ok ? pr : 0) * KE + cb) + ch * 16;
            cp_async16(bA + sw128(row * 128 + ch * 16), g, ok);
        }
        CP_COMMIT();
    };

    load_chunk(0, 0);
    load_chunk(1, 1);
    load_chunk(2, 2);

    for (int c = 0; c < NCHUNK; c++) {
        const int s = c % STAGES;
        if (c <= NCHUNK - 3) cp_wait<2>();
        else if (c == NCHUNK - 2) cp_wait<1>();
        else cp_wait<0>();
        __syncthreads();

        const uint32_t base = sb + s * STAGE_BYTES;
#pragma unroll
        for (int kk = 0; kk < 4; kk++) {
            uint32_t aF[4][4], bF[4][2];
#pragma unroll
            for (int im = 0; im < 4; im++)
                ldsm_x4(aF[im], base + aBase[im] + ((((kk * 2 + hiA) ^ aSel[im])) << 4));
#pragma unroll
            for (int in = 0; in < 4; in++)
                ldsm_x2(bF[in], base + bBase[in] + ((((kk * 2 + hiB) ^ bSel[in])) << 4));
#pragma unroll
            for (int im = 0; im < 4; im++)
#pragma unroll
                for (int in = 0; in < 4; in++)
                    mma_bf16(acc[im][in], aF[im], bF[in]);
        }

        if (c + STAGES < NCHUNK) {
            __syncthreads();                 // all warps done reading stage s
            load_chunk(c + STAGES, s);
        }
    }

    // ---- epilogue: scale by inv norms, float2 stores ----
    const int mrow0 = m0 + wm + (lane >> 2);     // + im*16, and +8 inside tile
    const int ncol0 = n0 + wn + (lane & 3) * 2;  // + in*8
#pragma unroll
    for (int im = 0; im < 4; im++) {
        const int mA = mrow0 + im * 16;
        const float ixn0 = inv_xn[mA];
        const float ixn1 = inv_xn[mA + 8];
        float* orow0 = out + (size_t)mA * C_ROWS;
        float* orow1 = out + (size_t)(mA + 8) * C_ROWS;
#pragma unroll
        for (int in = 0; in < 4; in++) {
            const int n = ncol0 + in * 8;
            if (n < C_ROWS) {
                float2 ipn = *reinterpret_cast<const float2*>(inv_pn + n);
                float2 v0, v1;
                v0.x = acc[im][in][0] * ixn0 * ipn.x;
                v0.y = acc[im][in][1] * ixn0 * ipn.y;
                v1.x = acc[im][in][2] * ixn1 * ipn.x;
                v1.y = acc[im][in][3] * ixn1 * ipn.y;
                *reinterpret_cast<float2*>(orow0 + n) = v0;
                *reinterpret_cast<float2*>(orow1 + n) = v1;
            }
        }
    }
}

// ---------------- launch ----------------
extern "C" void kernel_launch(void* const* d_in, const int* in_sizes, int n_in,
                              void* d_out, int out_size) {
    const float* x = (const float*)d_in[0];         // [16384, 256]
    const float* protos = (const float*)d_in[1];    // [10000, 256]
    float* out = (float*)d_out;                     // [16384, 10000]

    float *inv_xn, *inv_pn;
    __nv_bfloat16 *Xs, *Ps;
    cudaGetSymbolAddress((void**)&inv_xn, g_inv_xn);
    cudaGetSymbolAddress((void**)&inv_pn, g_inv_pn);
    cudaGetSymbolAddress((void**)&Xs, g_Xs);
    cudaGetSymbolAddress((void**)&Ps, g_Ps);

    row_inv_norm_kernel<<<(N_ROWS * 32 + 255) / 256, 256>>>(x, inv_xn, N_ROWS);
    row_inv_norm_kernel<<<(C_ROWS * 32 + 255) / 256, 256>>>(protos, inv_pn, C_ROWS);

    convert_split_kernel<0><<<(N_ROWS * (D_DIM / 4) + 255) / 256, 256>>>(x, Xs, N_ROWS);
    convert_split_kernel<1><<<(C_ROWS * (D_DIM / 4) + 255) / 256, 256>>>(protos, Ps, C_ROWS);

    cudaFuncSetAttribute(cosine_hmma_kernel,
                         cudaFuncAttributeMaxDynamicSharedMemorySize, SMEM_TOTAL);
    dim3 grid((C_ROWS + BN - 1) / BN, N_ROWS / BM);   // (79, 128)
    cosine_hmma_kernel<<<grid, 256, SMEM_TOTAL>>>(Xs, Ps, inv_xn, inv_pn, out);
}